// round 10
// baseline (speedup 1.0000x reference)
#include <cuda_runtime.h>

// SSIM loss, 16x3x512x512 f32, separable 11-tap Gaussian (sigma=1.5).
// TILE 32x64, 256-thread blocks, 4 blocks/SM. Element-streamed f32x2 H-conv
// (low register pressure, loads consumed immediately); A/B H-planes
// interleaved (LDS.128 V-pass); symmetric-tap dedup; fused deterministic
// reduction.

#define IMH 512
#define IMW 512
#define TILE_W 32
#define TILE_H 64
#define SROWS 74                // TILE_H + 10 halo
#define HP 32                   // h-plane row width (cols)
#define NBLK (16 * 8 * 48)      // 6144 blocks
#define OFF_C (SROWS * HP * 4)           // 9472 floats (AB interleaved plane)
#define SMEM_FLOATS (OFF_C + SROWS * HP) // 11840
#define SMEM_BYTES (SMEM_FLOATS * 4)     // 47360

typedef unsigned long long ull;

__device__ float g_partials[NBLK];
__device__ unsigned int g_count = 0;

static __device__ constexpr float Gw[11] = {
    0.00102838f, 0.00759876f, 0.03600078f, 0.10936070f, 0.21300553f,
    0.26601172f,
    0.21300553f, 0.10936070f, 0.03600078f, 0.00759876f, 0.00102838f};

__device__ __forceinline__ ull pk2(float lo, float hi) {
    ull r;
    asm("mov.b64 %0, {%1,%2};" : "=l"(r) : "f"(lo), "f"(hi));
    return r;
}
__device__ __forceinline__ void upk(ull v, float& lo, float& hi) {
    asm("mov.b64 {%0,%1}, %2;" : "=f"(lo), "=f"(hi) : "l"(v));
}
__device__ __forceinline__ ull f2fma(ull a, ull b, ull c) {
    ull d;
    asm("fma.rn.f32x2 %0, %1, %2, %3;" : "=l"(d) : "l"(a), "l"(b), "l"(c));
    return d;
}
__device__ __forceinline__ ull f2mul(ull a, ull b) {
    ull d;
    asm("mul.rn.f32x2 %0, %1, %2;" : "=l"(d) : "l"(a), "l"(b));
    return d;
}

// symmetric tap index: Gw[t] == Gw[10-t], keep 6 packed regs
#define TIX(t) ((t) < 6 ? (t) : 10 - (t))

extern "C" __global__ void __launch_bounds__(256, 4)
ssim_main(const float* __restrict__ gx, const float* __restrict__ gy,
          float* __restrict__ out) {
    extern __shared__ float sm[];
    __shared__ int s_last;

    const int tid = threadIdx.x;
    const int bx = blockIdx.x, by = blockIdx.y, p = blockIdx.z;
    const int c0 = bx * TILE_W;
    const int r0 = by * TILE_H;
    const float* px = gx + (size_t)p * IMH * IMW;
    const float* py = gy + (size_t)p * IMH * IMW;

    ull GwP[6];
    #pragma unroll
    for (int t = 0; t < 6; t++) GwP[t] = pk2(Gw[t], Gw[t]);

    // ---------------- stage 1: horizontal conv, element-streamed f32x2 -----
    {
        const int tx = tid & 7;              // 8 groups of 4 output cols
        const int ty = tid >> 3;             // 0..31
        const int cb = tx * 4;
        const int gc0 = c0 + cb - 8;         // first window col (f4-aligned)
        const bool colsafe = (gc0 >= 0) && (gc0 + 19 < IMW);

        // consume window element k (0..19): scatter into the 4 outputs.
        // For output cc, tap t = k-3-cc; contributions arrive t-ascending
        // per output => accumulation order identical to the tap-loop form.
        auto elem = [&](const int k, const float x, const float y,
                        ull* accA, ull* accB, float* accC) {
            if (k < 3 || k > 16) return;     // compile-time pruned
            const ull v = pk2(x, y);
            const ull s = f2mul(v, v);
            const float c = x * y;
            #pragma unroll
            for (int cc = 0; cc < 4; cc++) {
                const int t = k - 3 - cc;
                if (t >= 0 && t < 11) {
                    accA[cc] = f2fma(v, GwP[TIX(t)], accA[cc]);
                    accB[cc] = f2fma(s, GwP[TIX(t)], accB[cc]);
                    accC[cc] = fmaf(c, Gw[t], accC[cc]);
                }
            }
        };

        auto do_row = [&](const int i) {
            const int gr = r0 - 5 + i;
            ull accA[4] = {0ull, 0ull, 0ull, 0ull};
            ull accB[4] = {0ull, 0ull, 0ull, 0ull};
            float accC[4] = {0.f, 0.f, 0.f, 0.f};

            if (gr >= 0 && gr < IMH) {
                const float* rowx = px + (size_t)gr * IMW;
                const float* rowy = py + (size_t)gr * IMW;
                if (colsafe) {
                    #pragma unroll
                    for (int j = 0; j < 5; j++) {
                        const float4 vx = *(const float4*)(rowx + gc0 + 4 * j);
                        const float4 vy = *(const float4*)(rowy + gc0 + 4 * j);
                        elem(4 * j + 0, vx.x, vy.x, accA, accB, accC);
                        elem(4 * j + 1, vx.y, vy.y, accA, accB, accC);
                        elem(4 * j + 2, vx.z, vy.z, accA, accB, accC);
                        elem(4 * j + 3, vx.w, vy.w, accA, accB, accC);
                    }
                } else {
                    #pragma unroll
                    for (int j = 0; j < 5; j++) {
                        float fx[4], fy[4];
                        #pragma unroll
                        for (int r = 0; r < 4; r++) {
                            const int c = gc0 + 4 * j + r;
                            const bool ok = (c >= 0) && (c < IMW);
                            fx[r] = ok ? rowx[c] : 0.f;
                            fy[r] = ok ? rowy[c] : 0.f;
                        }
                        elem(4 * j + 0, fx[0], fy[0], accA, accB, accC);
                        elem(4 * j + 1, fx[1], fy[1], accA, accB, accC);
                        elem(4 * j + 2, fx[2], fy[2], accA, accB, accC);
                        elem(4 * j + 3, fx[3], fy[3], accA, accB, accC);
                    }
                }
            }

            // interleaved AB plane: 16B per column = {(mux,muy),(Exx,Eyy)}
            {
                float* ab = sm + (size_t)(i * HP + cb) * 4;
                ((ulonglong2*)ab)[0] = make_ulonglong2(accA[0], accB[0]);
                ((ulonglong2*)ab)[1] = make_ulonglong2(accA[1], accB[1]);
                ((ulonglong2*)ab)[2] = make_ulonglong2(accA[2], accB[2]);
                ((ulonglong2*)ab)[3] = make_ulonglong2(accA[3], accB[3]);
            }
            *(float4*)(sm + OFF_C + i * HP + cb) =
                make_float4(accC[0], accC[1], accC[2], accC[3]);
        };

        do_row(ty);            // rows 0..31
        do_row(ty + 32);       // rows 32..63
        if (ty < SROWS - 64)   // rows 64..73
            do_row(ty + 64);
    }
    __syncthreads();

    // ---------------- stage 2: vertical conv (8-row strip) + SSIM ----------
    const int col = tid & 31;
    const int sgrp = tid >> 5;   // 0..7 strips of 8 output rows
    ull aA[8], aB[8];
    float aC[8];
    #pragma unroll
    for (int i = 0; i < 8; i++) { aA[i] = 0ull; aB[i] = 0ull; aC[i] = 0.f; }

    #pragma unroll
    for (int jr = 0; jr < 18; jr++) {
        const int hr = sgrp * 8 + jr;
        const ulonglong2 vab =
            *(const ulonglong2*)(sm + (size_t)(hr * HP + col) * 4);
        const float vC = sm[OFF_C + hr * HP + col];
        #pragma unroll
        for (int i = 0; i < 8; i++) {
            const int t = jr - i;
            if (t >= 0 && t < 11) {
                aA[i] = f2fma(vab.x, GwP[TIX(t)], aA[i]);
                aB[i] = f2fma(vab.y, GwP[TIX(t)], aB[i]);
                aC[i] = fmaf(vC, Gw[t], aC[i]);
            }
        }
    }

    float lsum = 0.f;
    #pragma unroll
    for (int i = 0; i < 8; i++) {
        float mux, muy, exx, eyy;
        upk(aA[i], mux, muy);
        upk(aB[i], exx, eyy);
        const float exy = aC[i];
        const float mux2 = mux * mux;
        const float muy2 = muy * muy;
        const float muxy = mux * muy;
        const float sx2 = exx - mux2;
        const float sy2 = eyy - muy2;
        const float sxy = exy - muxy;
        const float num = (2.f * muxy + 1e-4f) * (2.f * sxy + 9e-4f);
        const float den = (mux2 + muy2 + 1e-4f) * (sx2 + sy2 + 9e-4f) + 1e-12f;
        lsum += 1.f - __fdividef(num, den);
    }

    __syncthreads();   // stage-2 smem reads done before reuse
    #pragma unroll
    for (int o = 16; o > 0; o >>= 1)
        lsum += __shfl_down_sync(0xffffffffu, lsum, o);
    if ((tid & 31) == 0) sm[tid >> 5] = lsum;   // 8 warp sums
    __syncthreads();
    if (tid == 0) {
        float s = 0.f;
        #pragma unroll
        for (int w = 0; w < 8; w++) s += sm[w];
        g_partials[(p * 8 + by) * 16 + bx] = s;
        __threadfence();
        const unsigned int old = atomicAdd(&g_count, 1u);
        s_last = (old == NBLK - 1) ? 1 : 0;
    }
    __syncthreads();

    // ---------------- last block: deterministic final reduction ------------
    if (s_last) {
        double s = 0.0;
        for (int i = tid; i < NBLK; i += 256) s += (double)g_partials[i];
        double* sd = (double*)sm;
        sd[tid] = s;
        __syncthreads();
        #pragma unroll
        for (int o = 128; o > 0; o >>= 1) {
            if (tid < o) sd[tid] += sd[tid + o];
            __syncthreads();
        }
        if (tid == 0) {
            out[0] = (float)(sd[0] * (1.0 / 12582912.0));
            g_count = 0;  // reset for next graph replay
        }
    }
}

extern "C" void kernel_launch(void* const* d_in, const int* in_sizes, int n_in,
                              void* d_out, int out_size) {
    const float* x = (const float*)d_in[0];
    const float* y = (const float*)d_in[1];
    float* out = (float*)d_out;

    cudaFuncSetAttribute(ssim_main, cudaFuncAttributeMaxDynamicSharedMemorySize,
                         SMEM_BYTES);
    dim3 grid(IMW / TILE_W, IMH / TILE_H, 48);   // 16 x 8 x 48
    ssim_main<<<grid, 256, SMEM_BYTES>>>(x, y, out);
}

// round 12
// speedup vs baseline: 1.2135x; 1.2135x over previous
#include <cuda_runtime.h>

// SSIM loss, 16x3x512x512 f32, separable 11-tap Gaussian (sigma=1.5).
// Algebraic 2-stream form: conv{(x,y)} and conv{((x+y)^2,(x-y)^2)} packed
// f32x2; Exx+Eyy=(S+ + S-)/2, Exy=(S+ - S-)/4. smem 37.9KB -> 5 blocks/SM.
// TILE 32x64, batched loads (MLP preserved), scatter accumulation.

#define IMH 512
#define IMW 512
#define TILE_W 32
#define TILE_H 64
#define SROWS 74                // TILE_H + 10 halo
#define HP 32                   // h-plane row width (cols)
#define NBLK (16 * 8 * 48)      // 6144 blocks
#define SMEM_FLOATS (SROWS * HP * 4)   // 9472 floats (2 ull per col)
#define SMEM_BYTES (SMEM_FLOATS * 4)   // 37888

typedef unsigned long long ull;

__device__ float g_partials[NBLK];
__device__ unsigned int g_count = 0;

static __device__ constexpr float Gw[11] = {
    0.00102838f, 0.00759876f, 0.03600078f, 0.10936070f, 0.21300553f,
    0.26601172f,
    0.21300553f, 0.10936070f, 0.03600078f, 0.00759876f, 0.00102838f};

__device__ __forceinline__ ull pk2(float lo, float hi) {
    ull r;
    asm("mov.b64 %0, {%1,%2};" : "=l"(r) : "f"(lo), "f"(hi));
    return r;
}
__device__ __forceinline__ void upk(ull v, float& lo, float& hi) {
    asm("mov.b64 {%0,%1}, %2;" : "=f"(lo), "=f"(hi) : "l"(v));
}
__device__ __forceinline__ ull f2fma(ull a, ull b, ull c) {
    ull d;
    asm("fma.rn.f32x2 %0, %1, %2, %3;" : "=l"(d) : "l"(a), "l"(b), "l"(c));
    return d;
}
__device__ __forceinline__ ull f2mul(ull a, ull b) {
    ull d;
    asm("mul.rn.f32x2 %0, %1, %2;" : "=l"(d) : "l"(a), "l"(b));
    return d;
}

// symmetric tap index: Gw[t] == Gw[10-t], keep 6 packed regs
#define TIX(t) ((t) < 6 ? (t) : 10 - (t))

extern "C" __global__ void __launch_bounds__(256, 5)
ssim_main(const float* __restrict__ gx, const float* __restrict__ gy,
          float* __restrict__ out) {
    extern __shared__ float sm[];
    __shared__ int s_last;

    const int tid = threadIdx.x;
    const int bx = blockIdx.x, by = blockIdx.y, p = blockIdx.z;
    const int c0 = bx * TILE_W;
    const int r0 = by * TILE_H;
    const float* px = gx + (size_t)p * IMH * IMW;
    const float* py = gy + (size_t)p * IMH * IMW;

    ull GwP[6];
    #pragma unroll
    for (int t = 0; t < 6; t++) GwP[t] = pk2(Gw[t], Gw[t]);

    // ---------------- stage 1: horizontal conv, 2 packed streams -----------
    {
        const int tx = tid & 7;              // 8 groups of 4 output cols
        const int ty = tid >> 3;             // 0..31
        const int cb = tx * 4;
        const int gc0 = c0 + cb - 8;         // first window col (f4-aligned)
        const bool colsafe = (gc0 >= 0) && (gc0 + 19 < IMW);

        // consume window element k: scatter into 4 outputs (t ascending).
        auto elem = [&](const int k, const float x, const float y,
                        ull* a1, ull* a2) {
            if (k < 3 || k > 16) return;     // compile-time pruned
            const ull v = pk2(x, y);
            ull w = pk2(x + y, x - y);
            w = f2mul(w, w);
            #pragma unroll
            for (int cc = 0; cc < 4; cc++) {
                const int t = k - 3 - cc;
                if (t >= 0 && t < 11) {
                    a1[cc] = f2fma(v, GwP[TIX(t)], a1[cc]);
                    a2[cc] = f2fma(w, GwP[TIX(t)], a2[cc]);
                }
            }
        };

        auto do_row = [&](const int i) {
            const int gr = r0 - 5 + i;
            ull a1[4] = {0ull, 0ull, 0ull, 0ull};
            ull a2[4] = {0ull, 0ull, 0ull, 0ull};

            if (gr >= 0 && gr < IMH) {
                const float* rowx = px + (size_t)gr * IMW;
                const float* rowy = py + (size_t)gr * IMW;
                if (colsafe) {
                    // batch 1: chunks 0..1 (elems 0..7), 4 loads in flight
                    float4 vx0 = *(const float4*)(rowx + gc0);
                    float4 vy0 = *(const float4*)(rowy + gc0);
                    float4 vx1 = *(const float4*)(rowx + gc0 + 4);
                    float4 vy1 = *(const float4*)(rowy + gc0 + 4);
                    elem(3, vx0.w, vy0.w, a1, a2);
                    elem(4, vx1.x, vy1.x, a1, a2);
                    elem(5, vx1.y, vy1.y, a1, a2);
                    elem(6, vx1.z, vy1.z, a1, a2);
                    elem(7, vx1.w, vy1.w, a1, a2);
                    // batch 2: chunks 2..4 (elems 8..16), 6 loads in flight
                    float4 vx2 = *(const float4*)(rowx + gc0 + 8);
                    float4 vy2 = *(const float4*)(rowy + gc0 + 8);
                    float4 vx3 = *(const float4*)(rowx + gc0 + 12);
                    float4 vy3 = *(const float4*)(rowy + gc0 + 12);
                    float4 vx4 = *(const float4*)(rowx + gc0 + 16);
                    float4 vy4 = *(const float4*)(rowy + gc0 + 16);
                    elem(8,  vx2.x, vy2.x, a1, a2);
                    elem(9,  vx2.y, vy2.y, a1, a2);
                    elem(10, vx2.z, vy2.z, a1, a2);
                    elem(11, vx2.w, vy2.w, a1, a2);
                    elem(12, vx3.x, vy3.x, a1, a2);
                    elem(13, vx3.y, vy3.y, a1, a2);
                    elem(14, vx3.z, vy3.z, a1, a2);
                    elem(15, vx3.w, vy3.w, a1, a2);
                    elem(16, vx4.x, vy4.x, a1, a2);
                } else {
                    #pragma unroll
                    for (int k = 3; k <= 16; k++) {
                        const int c = gc0 + k;
                        const bool ok = (c >= 0) && (c < IMW);
                        const float x = ok ? rowx[c] : 0.f;
                        const float y = ok ? rowy[c] : 0.f;
                        elem(k, x, y, a1, a2);
                    }
                }
            }

            // interleaved plane: 16B per col = {(mux,muy),(S+,S-)} partials
            float* ab = sm + (size_t)(i * HP + cb) * 4;
            ((ulonglong2*)ab)[0] = make_ulonglong2(a1[0], a2[0]);
            ((ulonglong2*)ab)[1] = make_ulonglong2(a1[1], a2[1]);
            ((ulonglong2*)ab)[2] = make_ulonglong2(a1[2], a2[2]);
            ((ulonglong2*)ab)[3] = make_ulonglong2(a1[3], a2[3]);
        };

        do_row(ty);            // rows 0..31
        do_row(ty + 32);       // rows 32..63
        if (ty < SROWS - 64)   // rows 64..73
            do_row(ty + 64);
    }
    __syncthreads();

    // ---------------- stage 2: vertical conv (8-row strip) + SSIM ----------
    const int col = tid & 31;
    const int sgrp = tid >> 5;   // 0..7 strips of 8 output rows
    ull aA[8], aB[8];
    #pragma unroll
    for (int i = 0; i < 8; i++) { aA[i] = 0ull; aB[i] = 0ull; }

    #pragma unroll
    for (int jr = 0; jr < 18; jr++) {
        const int hr = sgrp * 8 + jr;
        const ulonglong2 vab =
            *(const ulonglong2*)(sm + (size_t)(hr * HP + col) * 4);
        #pragma unroll
        for (int i = 0; i < 8; i++) {
            const int t = jr - i;
            if (t >= 0 && t < 11) {
                aA[i] = f2fma(vab.x, GwP[TIX(t)], aA[i]);
                aB[i] = f2fma(vab.y, GwP[TIX(t)], aB[i]);
            }
        }
    }

    float lsum = 0.f;
    #pragma unroll
    for (int i = 0; i < 8; i++) {
        float mux, muy, sp, sn;
        upk(aA[i], mux, muy);
        upk(aB[i], sp, sn);
        const float exx_eyy = (sp + sn) * 0.5f;   // Exx + Eyy
        const float exy     = (sp - sn) * 0.25f;  // Exy
        const float mux2 = mux * mux;
        const float muy2 = muy * muy;
        const float muxy = mux * muy;
        const float sigsum = exx_eyy - mux2 - muy2;  // sigma_x2 + sigma_y2
        const float sxy = exy - muxy;
        const float num = (2.f * muxy + 1e-4f) * (2.f * sxy + 9e-4f);
        const float den = (mux2 + muy2 + 1e-4f) * (sigsum + 9e-4f) + 1e-12f;
        lsum += 1.f - __fdividef(num, den);
    }

    __syncthreads();   // stage-2 smem reads done before reuse
    #pragma unroll
    for (int o = 16; o > 0; o >>= 1)
        lsum += __shfl_down_sync(0xffffffffu, lsum, o);
    if ((tid & 31) == 0) sm[tid >> 5] = lsum;   // 8 warp sums
    __syncthreads();
    if (tid == 0) {
        float s = 0.f;
        #pragma unroll
        for (int w = 0; w < 8; w++) s += sm[w];
        g_partials[(p * 8 + by) * 16 + bx] = s;
        __threadfence();
        const unsigned int old = atomicAdd(&g_count, 1u);
        s_last = (old == NBLK - 1) ? 1 : 0;
    }
    __syncthreads();

    // ---------------- last block: deterministic final reduction ------------
    if (s_last) {
        double s = 0.0;
        for (int i = tid; i < NBLK; i += 256) s += (double)g_partials[i];
        double* sd = (double*)sm;
        sd[tid] = s;
        __syncthreads();
        #pragma unroll
        for (int o = 128; o > 0; o >>= 1) {
            if (tid < o) sd[tid] += sd[tid + o];
            __syncthreads();
        }
        if (tid == 0) {
            out[0] = (float)(sd[0] * (1.0 / 12582912.0));
            g_count = 0;  // reset for next graph replay
        }
    }
}

extern "C" void kernel_launch(void* const* d_in, const int* in_sizes, int n_in,
                              void* d_out, int out_size) {
    const float* x = (const float*)d_in[0];
    const float* y = (const float*)d_in[1];
    float* out = (float*)d_out;

    cudaFuncSetAttribute(ssim_main, cudaFuncAttributeMaxDynamicSharedMemorySize,
                         SMEM_BYTES);
    dim3 grid(IMW / TILE_W, IMH / TILE_H, 48);   // 16 x 8 x 48
    ssim_main<<<grid, 256, SMEM_BYTES>>>(x, y, out);
}